// round 14
// baseline (speedup 1.0000x reference)
#include <cuda_runtime.h>
#include <math.h>

// ---------------------------------------------------------------------------
// R14: fused KAN generator, 512 blocks x 256 threads, prep kernel for weights.
// vs R13:
//  * closed-form featurize: three nonzero quadratic B-spline bases computed
//    directly (q0=(1-t)^2/2, q1=1-q0-q2, q2=t^2/2) and placed by slot selects
//    (out-of-grid values fall through to 0 automatically) — ~half the instrs
//  * activations stored as float4-per-pixel (channels vectorized): phase-C
//    output is one STS.128, featurize input one LDS.128 per pixel
// Phase-C FFMA order identical to R13.
// ---------------------------------------------------------------------------

#define F0A make_float4(0.0f, 0.125f, 0.75f, 0.125f)
#define F0B make_float2(0.0f, 0.0f)

__device__ float4 g_wsh[4 * 384];

__device__ __forceinline__ float ftanh(float x) {
    float e = __expf(2.0f * x);
    return 1.0f - __fdividef(2.0f, e + 1.0f);
}

// closed-form quadratic B-spline features + relu
__device__ __forceinline__ void feats(float v, float4& fa, float2& fb) {
    float u  = fmaf(v, 1.5f, 3.5f);
    float kf = floorf(u);
    float t  = u - kf;
    int   k  = (int)kf;
    float q2 = 0.5f * t * t;
    float om = 1.0f - t;
    float q0 = 0.5f * om * om;
    float q1 = 1.0f - q0 - q2;
    float s0 = (k == 0) ? q2 : (k == 1) ? q1 : (k == 2) ? q0 : 0.0f;
    float s1 = (k == 1) ? q2 : (k == 2) ? q1 : (k == 3) ? q0 : 0.0f;
    float s2 = (k == 2) ? q2 : (k == 3) ? q1 : (k == 4) ? q0 : 0.0f;
    float s3 = (k == 3) ? q2 : (k == 4) ? q1 : (k == 5) ? q0 : 0.0f;
    float s4 = (k == 4) ? q2 : (k == 5) ? q1 : (k == 6) ? q0 : 0.0f;
    fa = make_float4(s0, s1, s2, s3);
    fb = make_float2(s4, fmaxf(v, 0.0f));
}

template <int COUT>
__device__ __forceinline__ void fmaC(float s, float4 w, float4& a) {
    a.x = fmaf(s, w.x, a.x);
    a.y = fmaf(s, w.y, a.y);
    a.z = fmaf(s, w.z, a.z);
    if (COUT == 4) a.w = fmaf(s, w.w, a.w);
}

// ----------------------------- prep kernel ---------------------------------
__global__ void prep_weights(
    const float* __restrict__ bw1, const float* __restrict__ sw1,
    const float* __restrict__ bw2, const float* __restrict__ sw2,
    const float* __restrict__ bw3, const float* __restrict__ sw3,
    const float* __restrict__ bw4, const float* __restrict__ sw4)
{
    int idx = blockIdx.x * 256 + threadIdx.x;
    if (idx >= 4 * 1536) return;
    int s = idx / 1536, e = idx % 1536;
    const float* bw = (s == 0) ? bw1 : (s == 1) ? bw2 : (s == 2) ? bw3 : bw4;
    const float* sw = (s == 0) ? sw1 : (s == 1) ? sw2 : (s == 2) ? sw3 : sw4;
    const int COUT = (s == 3) ? 3 : 4;

    int co  = e & 3;
    int wf  = (e >> 2) % 6;
    int c   = (e / 24) & 3;
    int pos = (e / 96) & 3;
    int p   = e / 384;
    int py = p >> 1, px = p & 1;
    int ry = pos >> 1, rx = pos & 1;
    float val = 0.0f;
    if (co < COUT) {
        int ky0 = ry * (1 + py), nky = 1 + (ry ^ py);
        int kx0 = rx * (1 + px), nkx = 1 + (rx ^ px);
        for (int a = 0; a < nky; a++)
            for (int bb = 0; bb < nkx; bb++) {
                int j = c * 9 + (ky0 + a) * 3 + (kx0 + bb);
                val += (wf == 5) ? bw[co * 36 + j]
                                 : sw[(co * 36 + j) * 5 + wf];
            }
    }
    reinterpret_cast<float*>(g_wsh)[idx] = val;
}

// ----------------------------- one conv stage ------------------------------
template <int HIN, int COUT, bool FINAL, int NPX>
__device__ __forceinline__ void do_stage(
    const float4* __restrict__ gw,
    float4* act4, float4* featA, float2* featB, float4* fbP,
    float4* wsh4, float* gout)
{
    constexpr int S2    = HIN * HIN;
    constexpr int HOUT  = 2 * HIN;
    constexpr int HP    = HIN + 2;
    constexpr int S2P   = HP * HP;
    constexpr int ACT_L = S2 / NPX;                 // active lanes per parity
    constexpr int JSTR  = (NPX > 1) ? ACT_L / HIN : 1;
    constexpr bool PAIR = (NPX >= 2);
    constexpr int POFF  = PAIR ? (JSTR * NPX / 2) : 1;  // row-pair offset
    constexpr int S2FB  = (HP - POFF) * HP;         // fbP slots per channel
    const int tid = threadIdx.x;

    // --- copy combined weights from global (coalesced, L2-hot)
#pragma unroll
    for (int k = 0; k < 2; k++) {
        int i = tid + k * 256;
        if (i < 384) wsh4[i] = __ldg(gw + i);
    }

    // --- border ring: spline(0) features (zero-padding contribution)
    {
        constexpr int NB = 2 * HP + 2 * HIN;
        for (int e = tid; e < 4 * NB; e += 256) {
            int c = e / NB, r = e % NB;
            int y, x;
            if (r < 2 * HP) { y = (r < HP) ? 0 : HP - 1; x = (r < HP) ? r : r - HP; }
            else { int r2 = r - 2 * HP;
                   y = 1 + ((r2 < HIN) ? r2 : r2 - HIN);
                   x = (r2 < HIN) ? 0 : HP - 1; }
            featA[c * S2P + y * HP + x] = F0A;
            if (PAIR) {
                if (y <= HP - 1 - POFF) {
                    float2* q = reinterpret_cast<float2*>(
                        &fbP[c * S2FB + y * HP + x]);
                    q[0] = F0B;
                }
                if (y >= POFF) {
                    float2* q = reinterpret_cast<float2*>(
                        &fbP[c * S2FB + (y - POFF) * HP + x]);
                    q[1] = F0B;
                }
            } else {
                featB[c * S2P + y * HP + x] = F0B;
            }
        }
    }

    // --- featurize interior source pixels (all 4 channels from one LDS.128)
#pragma unroll
    for (int k = 0; k < (S2 + 255) / 256; k++) {
        int pix = tid + k * 256;
        if (S2 >= 256 || pix < S2) {
            int y = pix / HIN, x = pix % HIN;
            float4 vals = act4[pix];
            int yp = y + 1, xp = x + 1;
#pragma unroll
            for (int c = 0; c < 4; c++) {
                float v = (c == 0) ? vals.x : (c == 1) ? vals.y
                        : (c == 2) ? vals.z : vals.w;
                float4 fa; float2 fb;
                feats(v, fa, fb);
                featA[c * S2P + yp * HP + xp] = fa;
                if (PAIR) {
                    if (yp <= HP - 1 - POFF) {
                        float2* q = reinterpret_cast<float2*>(
                            &fbP[c * S2FB + yp * HP + xp]);
                        q[0] = fb;
                    }
                    if (yp >= POFF) {
                        float2* q = reinterpret_cast<float2*>(
                            &fbP[c * S2FB + (yp - POFF) * HP + xp]);
                        q[1] = fb;
                    }
                } else {
                    featB[c * S2P + yp * HP + xp] = fb;
                }
            }
        }
    }
    __syncthreads();

    // --- phase C
    const int p  = tid >> 6;       // warp-uniform parity
    const int l  = tid & 63;
    const int py = p >> 1, px = p & 1;

    if (ACT_L >= 64 || l < ACT_L) {
        const int Yb = l / HIN;
        const int X  = l % HIN;
        const int base = (Yb + py) * HP + X + px;

        float4 acc[NPX];
#pragma unroll
        for (int j = 0; j < NPX; j++) acc[j] = make_float4(0.f, 0.f, 0.f, 0.f);

#pragma unroll
        for (int pos = 0; pos < 4; pos++) {
            const int ry = pos >> 1, rx = pos & 1;
            const float4* wp = wsh4 + (p * 4 + pos) * 24;
#pragma unroll
            for (int c = 0; c < 4; c++) {
                const int off = base + c * S2P + ry * HP + rx;
                float4 fa[NPX];
                float2 fbv[(NPX > 1) ? 1 : NPX];
                float4 fbQ[(NPX >= 2) ? NPX / 2 : 1];
#pragma unroll
                for (int j = 0; j < NPX; j++)
                    fa[j] = featA[off + j * JSTR * HP];
                if (PAIR) {
                    const int offb = c * S2FB + base + ry * HP + rx;
#pragma unroll
                    for (int k = 0; k < NPX / 2; k++)
                        fbQ[k] = fbP[offb + k * JSTR * HP];
                } else {
                    fbv[0] = featB[off];
                }
                const float4* w = wp + c * 6;
#pragma unroll
                for (int f = 0; f < 6; f++) {
                    float4 wv = w[f];
#pragma unroll
                    for (int j = 0; j < NPX; j++) {
                        float s;
                        if (f < 4) {
                            s = (f == 0) ? fa[j].x : (f == 1) ? fa[j].y
                              : (f == 2) ? fa[j].z : fa[j].w;
                        } else if (PAIR) {
                            s = (j < NPX / 2)
                              ? ((f == 4) ? fbQ[j].x : fbQ[j].y)
                              : ((f == 4) ? fbQ[j - NPX / 2].z
                                          : fbQ[j - NPX / 2].w);
                        } else {
                            s = (f == 4) ? fbv[0].x : fbv[0].y;
                        }
                        fmaC<COUT>(s, wv, acc[j]);
                    }
                }
            }
        }

        // --- write outputs
#pragma unroll
        for (int j = 0; j < NPX; j++) {
            int Y = Yb + j * JSTR;
            int y = 2 * Y + py, x = 2 * X + px;
            if (FINAL) {
                gout[0 * HOUT * HOUT + y * HOUT + x] = ftanh(acc[j].x);
                gout[1 * HOUT * HOUT + y * HOUT + x] = ftanh(acc[j].y);
                gout[2 * HOUT * HOUT + y * HOUT + x] = ftanh(acc[j].z);
            } else {
                act4[y * HOUT + x] = acc[j];     // one STS.128
            }
        }
    }
    __syncthreads();
}

// ----------------------------- fused kernel --------------------------------
__global__ void __launch_bounds__(256, 4) fused_kan_kernel(
    const float* __restrict__ x,
    const float* __restrict__ lin_w,
    const float* __restrict__ lin_b,
    float* __restrict__ out)
{
    __shared__ float4 act4[256];            // [pixel] -> channels in vector
    __shared__ float4 featA[4 * 18 * 18];   // stage-4 sized, reused
    __shared__ float2 featB[4 * 6 * 6];     // non-pair stages (1,2)
    __shared__ float4 fbP[4 * 10 * 18];     // pair-packed fb (stages 3,4)
    __shared__ float4 wsh4[384];

    const int tid = threadIdx.x;
    const int b   = blockIdx.x;

    // linear + relu: 16 outputs, 4 threads each over 25-element chunks.
    // output j = c*4 + pix  (c-major reshape [4,2,2]) -> component c of act4[pix]
    if (tid < 64) {
        int j = tid >> 2, qp = tid & 3;
        const float* xr = x + b * 100 + qp * 25;
        const float* wr = lin_w + j * 100 + qp * 25;
        float acc = 0.0f;
#pragma unroll
        for (int i = 0; i < 25; i++) acc = fmaf(xr[i], wr[i], acc);
        acc += __shfl_xor_sync(0xffffffffu, acc, 1);
        acc += __shfl_xor_sync(0xffffffffu, acc, 2);
        if (qp == 0) {
            int c = j >> 2, pix = j & 3;
            reinterpret_cast<float*>(act4)[pix * 4 + c] =
                fmaxf(acc + lin_b[j], 0.0f);
        }
    }
    __syncthreads();

    do_stage<2, 4, false, 1>(g_wsh,        act4, featA, featB, fbP, wsh4, nullptr);
    do_stage<4, 4, false, 1>(g_wsh + 384,  act4, featA, featB, fbP, wsh4, nullptr);
    do_stage<8, 4, false, 2>(g_wsh + 768,  act4, featA, featB, fbP, wsh4, nullptr);
    do_stage<16, 3, true, 4>(g_wsh + 1152, act4, featA, featB, fbP, wsh4,
                             out + (size_t)b * 3 * 32 * 32);
}

// ---------------------------------------------------------------------------
extern "C" void kernel_launch(void* const* d_in, const int* in_sizes, int n_in,
                              void* d_out, int out_size) {
    const float* x     = (const float*)d_in[0];
    const float* lin_w = (const float*)d_in[1];
    const float* lin_b = (const float*)d_in[2];
    const float* bw1   = (const float*)d_in[3];
    const float* sw1   = (const float*)d_in[4];
    const float* bw2   = (const float*)d_in[5];
    const float* sw2   = (const float*)d_in[6];
    const float* bw3   = (const float*)d_in[7];
    const float* sw3   = (const float*)d_in[8];
    const float* bw4   = (const float*)d_in[9];
    const float* sw4   = (const float*)d_in[10];

    prep_weights<<<24, 256>>>(bw1, sw1, bw2, sw2, bw3, sw3, bw4, sw4);
    fused_kan_kernel<<<512, 256>>>(x, lin_w, lin_b, (float*)d_out);
}